// round 14
// baseline (speedup 1.0000x reference)
#include <cuda_runtime.h>
#include <cuda_fp16.h>
#include <math.h>
#include <stdint.h>

#define T_STEPS 256
#define BATCH   256
#define IN_DIM  512
#define H_DIM   512
#define GATES   2048

// ---------------- device scratch -------------------------------------------
__device__ float    g_Xg[(size_t)T_STEPS * BATCH * GATES];   // x@Wih^T + b (512MB)
__device__ unsigned g_xfr[(size_t)512 * 32 * 8 * 32 * 4];    // x fp16 A-frags (64MB)
__device__ unsigned g_wfr[64 * 4 * 32 * 32 * 2];             // Wih fp16 B-frags (2MB)
__device__ unsigned g_Wph[16 * 4 * 4 * 32 * 32 * 2];         // W_hh fp16 B-frags (2MB)
__device__ unsigned g_APg[2 * 8 * 32 * 2 * 32 * 4];          // fp16 h frags, dbl-buf
__device__ unsigned g_cnt[8 * 32];                           // per-group barrier
__device__ unsigned g_gen[8 * 32];

// ---------------- helpers --------------------------------------------------
__device__ __forceinline__ float sigm(float v) { return 1.0f / (1.0f + expf(-v)); }

__device__ __forceinline__ void mma_f16(float* c, uint4 A, uint2 B) {
    asm volatile(
        "mma.sync.aligned.m16n8k16.row.col.f32.f16.f16.f32 "
        "{%0,%1,%2,%3},{%4,%5,%6,%7},{%8,%9},{%0,%1,%2,%3};"
        : "+f"(c[0]), "+f"(c[1]), "+f"(c[2]), "+f"(c[3])
        : "r"(A.x), "r"(A.y), "r"(A.z), "r"(A.w), "r"(B.x), "r"(B.y));
}

__device__ __forceinline__ unsigned atom_add_acqrel(unsigned* p, unsigned v) {
    unsigned o;
    asm volatile("atom.acq_rel.gpu.global.add.u32 %0, [%1], %2;"
                 : "=r"(o) : "l"(p), "r"(v) : "memory");
    return o;
}
__device__ __forceinline__ void st_release(unsigned* p, unsigned v) {
    asm volatile("st.release.gpu.global.u32 [%0], %1;" :: "l"(p), "r"(v) : "memory");
}
__device__ __forceinline__ unsigned ld_acquire(const unsigned* p) {
    unsigned v;
    asm volatile("ld.acquire.gpu.global.u32 %0, [%1];" : "=r"(v) : "l"(p) : "memory");
    return v;
}

// ---------------- prep: x fp32 -> fp16 mma A-fragments ----------------------
// layout: [mtile 512][kb 32][mf 8][lane 32][reg 4] u32
__global__ void prep_x_frag(const float* __restrict__ x) {
    int id = blockIdx.x * blockDim.x + threadIdx.x;   // < 16777216
    int m = id >> 8, kp = id & 255;
    float2 v = ((const float2*)x)[(size_t)m * 256 + kp];
    __half2 h2 = __floats2half2_rn(v.x, v.y);
    int mtile = m >> 7, mf = (m >> 4) & 7, row = m & 15;
    int kb = kp >> 3;
    int lane = ((row & 7) << 2) | (kp & 3);
    int reg = ((row >> 3) & 1) | (((kp >> 2) & 1) << 1);
    g_xfr[((((size_t)mtile * 32 + kb) * 8 + mf) * 32 + lane) * 4 + reg] =
        *(unsigned*)&h2;
}

// ---------------- prep: Wih fp32 -> fp16 mma B-fragments --------------------
// layout: [ns 64][n8 4][kb 32][lane 32][reg 2] u32
__global__ void prep_w_frag(const float* __restrict__ Wih) {
    int id = blockIdx.x * blockDim.x + threadIdx.x;   // < 524288
    int n = id >> 8, kp = id & 255;
    float2 v = ((const float2*)Wih)[(size_t)n * 256 + kp];
    __half2 h2 = __floats2half2_rn(v.x, v.y);
    int ns = n >> 5, n8 = (n >> 3) & 3;
    int kb = kp >> 3;
    int lane = ((n & 7) << 2) | (kp & 3);
    int reg = (kp >> 2) & 1;
    g_wfr[((((size_t)ns * 4 + n8) * 32 + kb) * 32 + lane) * 2 + reg] =
        *(unsigned*)&h2;
}

// ---------------- prep: fp16 B-fragments for W_hh (lstm path) ---------------
__global__ void prep_hh(const float* __restrict__ Whh) {
    int t = blockIdx.x * blockDim.x + threadIdx.x;     // < 2^19
    int n = t >> 8, kp = t & 255, k = kp * 2;
    float2 wv = ((const float2*)Whh)[(size_t)n * 256 + kp];
    __half2 h2 = __floats2half2_rn(wv.x, wv.y);
    int g  = n >> 9, hh = n & 511;
    int ht = hh >> 5, hg = (hh >> 3) & 3;
    int kb16 = k >> 4;
    int lanei = ((n & 7) << 2) | ((k & 7) >> 1);
    int reg = (k >> 3) & 1;
    size_t bi = ((((size_t)(ht * 4 + g) * 4 + hg) * 32 + kb16) * 32 + lanei) * 2 + reg;
    g_Wph[bi] = *(unsigned*)&h2;
}

// ---------------- xgemm: fp16 mma.sync, m-stationary, warp-specialized ------
// 512 blocks; block = 128 m-rows, A frags in smem (128KB).
// 4 MMA warps (warp = m32 x full n32 slice), 4 copy warps stream W slices
// into a double buffer. 64 slices of 32 cols.
#define XG_SMEM ((32768 + 2 * 8192 + 2048) * 4)   // 200KB

__global__ __launch_bounds__(256, 1) void xgemm_f16(
    const float* __restrict__ bih, const float* __restrict__ bhh)
{
    extern __shared__ float sm_dyn[];
    unsigned* As = (unsigned*)sm_dyn;                // 32768 u32
    unsigned* Wb[2] = {As + 32768, As + 32768 + 8192};
    float* bias = (float*)(As + 32768 + 16384);      // 2048 f32

    const int tid = threadIdx.x, lane = tid & 31, w = tid >> 5;
    const int m0 = blockIdx.x * 128;
    const bool is_mma = (w < 4);
    const int mh = w & 3;
    const int htid = tid - 128;                      // helper index 0..127

    // stage A fragments (verbatim copy), W slice 0, bias — all threads
    {
        const uint4* asrc = (const uint4*)g_xfr + (size_t)blockIdx.x * 8192;
        uint4* adst = (uint4*)As;
        #pragma unroll
        for (int i = 0; i < 32; i++) adst[tid + i * 256] = __ldg(asrc + tid + i * 256);
        const uint4* wsrc = (const uint4*)g_wfr;
        uint4* wdst = (uint4*)Wb[0];
        #pragma unroll
        for (int i = 0; i < 8; i++) wdst[tid + i * 256] = __ldg(wsrc + tid + i * 256);
        #pragma unroll
        for (int i = 0; i < 8; i++) {
            int n = tid + i * 256;
            bias[n] = __ldg(&bih[n]) + __ldg(&bhh[n]);
        }
    }
    __syncthreads();

    const int r = m0 + mh * 32 + (lane >> 2);
    const int cb = (lane & 3) * 2;

    for (int i = 0; i < 64; i++) {
        const int cur = i & 1;

        if (!is_mma) {
            // copy warps: prefetch next W slice into the other buffer
            if (i + 1 < 64) {
                const uint4* ws = (const uint4*)g_wfr + (size_t)(i + 1) * 2048;
                uint4* wd = (uint4*)Wb[cur ^ 1];
                #pragma unroll
                for (int j = 0; j < 16; j++)
                    wd[htid + j * 128] = __ldg(ws + htid + j * 128);
            }
        } else {
            float acc[2][4][4] = {};        // [mfrag][n8][creg]
            const unsigned* Wc = Wb[cur];
            #pragma unroll 8
            for (int kb = 0; kb < 32; kb++) {
                uint4 A0 = *(const uint4*)&As[((kb * 8 + mh * 2 + 0) * 32 + lane) * 4];
                uint4 A1 = *(const uint4*)&As[((kb * 8 + mh * 2 + 1) * 32 + lane) * 4];
                #pragma unroll
                for (int n8 = 0; n8 < 4; n8++) {
                    uint2 B = *(const uint2*)&Wc[((n8 * 32 + kb) * 32 + lane) * 2];
                    mma_f16(acc[0][n8], A0, B);
                    mma_f16(acc[1][n8], A1, B);
                }
            }
            // epilogue: +bias, streaming stores (g_Xg layout unchanged)
            const int c0 = i * 32 + cb;
            #pragma unroll
            for (int n8 = 0; n8 < 4; n8++) {
                int c = c0 + n8 * 8;
                float b0 = bias[c], b1 = bias[c + 1];
                #pragma unroll
                for (int mf = 0; mf < 2; mf++) {
                    int row = r + mf * 16;
                    __stcs((float2*)&g_Xg[(size_t)row * GATES + c],
                           make_float2(acc[mf][n8][0] + b0, acc[mf][n8][1] + b1));
                    __stcs((float2*)&g_Xg[(size_t)(row + 8) * GATES + c],
                           make_float2(acc[mf][n8][2] + b0, acc[mf][n8][3] + b1));
                }
            }
        }
        __syncthreads();
    }
}

// ---------------- persistent LSTM recurrence, warp-specialized --------------
// 128 blocks = 8 b-groups x 16 hh-tiles. Block tile: 32 b x 32 hh x 4 gates.
// 4 MMA warps: warp hg = one 8-hh octet, ALL 4 gates, ALL 32 batch rows
// (m32n32). Fragment ownership == epilogue ownership; staging slot == lane.
// 4 helper warps: APg->APs copy, Stg flush, barrier. Arithmetic identical to
// the previous passing kernel (same fragments, same HMMA order).
__global__ __launch_bounds__(256, 1) void lstm_tc(
    const int*  __restrict__ dones,
    float* __restrict__ out_lstm,       // [T,B,H]
    float* __restrict__ out_hidden)     // [T,2,B,H]
{
    extern __shared__ float sm_dyn[];
    unsigned* Ws  = (unsigned*)sm_dyn;          // 32768 u32 (128KB)
    unsigned* APs = Ws + 32768;                 // 8192 u32  (32KB)
    unsigned* Stg = APs + 8192;                 // 512 u32   (2KB)

    const int tid = threadIdx.x, lane = tid & 31, w = tid >> 5;
    const int ht = blockIdx.x & 15, bt = blockIdx.x >> 4;
    const int hh0 = ht * 32, b0 = bt * 32;
    const bool is_mma = (w < 4);
    const int hg = w & 3;
    const int htid = tid - 128;

    const int rbase = b0 + (lane >> 2);             // rows rbase + 8j, j=0..3
    const int c0 = hh0 + hg * 8 + (lane & 3) * 2;   // hh column (even)

    // load W slice into smem once (verbatim fragment copy) — all threads
    {
        const uint4* src = (const uint4*)(g_Wph + (size_t)ht * 32768);
        uint4* dst = (uint4*)Ws;
        #pragma unroll
        for (int i = 0; i < 32; i++) dst[tid + i * 256] = src[tid + i * 256];
    }
    __syncthreads();

    unsigned* cnt = &g_cnt[bt * 32];
    unsigned* gen = &g_gen[bt * 32];
    const unsigned gbase = ld_acquire(gen);   // survives graph replays

    float h_st[8] = {0.f,0.f,0.f,0.f,0.f,0.f,0.f,0.f};   // [j*2+cc]
    float c_st[8] = {0.f,0.f,0.f,0.f,0.f,0.f,0.f,0.f};
    float keep[4];
    if (is_mma) {
        #pragma unroll
        for (int j = 0; j < 4; j++)
            keep[j] = 1.0f - (float)__ldg(&dones[rbase + 8 * j]);
    }

    for (int st = 0; st < T_STEPS; st++) {
        // prefetch Xg for this thread's 8 elements x 4 gates (MMA warps)
        float2 xv[4][4];
        if (is_mma) {
            #pragma unroll
            for (int j = 0; j < 4; j++) {
                const float* xg = g_Xg + ((size_t)st * BATCH + rbase + 8 * j) * GATES + c0;
                #pragma unroll
                for (int g = 0; g < 4; g++)
                    xv[j][g] = __ldcs((const float2*)(xg + g * H_DIM));
            }
        }

        float acc[2][4][4] = {};        // [mfrag][gate][creg]
        if (st > 0) {
            if (!is_mma) {
                // helpers: copy A fragments (32KB) from L2 into smem
                const uint4* asrc = (const uint4*)(g_APg + ((size_t)(st & 1) * 8 + bt) * 8192);
                uint4* adst = (uint4*)APs;
                #pragma unroll
                for (int i = 0; i < 16; i++)
                    adst[htid + i * 128] = __ldcg(asrc + htid + i * 128);
            }
            __syncthreads();
            if (is_mma) {
                #pragma unroll 4
                for (int kb = 0; kb < 32; kb++) {
                    uint4 A0 = *(const uint4*)&APs[((kb * 2 + 0) * 32 + lane) * 4];
                    uint4 A1 = *(const uint4*)&APs[((kb * 2 + 1) * 32 + lane) * 4];
                    #pragma unroll
                    for (int g = 0; g < 4; g++) {
                        uint2 B = *(const uint2*)&Ws[(((g * 4 + hg) * 32 + kb) * 32 + lane) * 2];
                        mma_f16(acc[0][g], A0, B);
                        mma_f16(acc[1][g], A1, B);
                    }
                }
            }
        }

        // epilogue (MMA warps): 8 elements = rows rbase+8j x cols c0,c0+1
        float hp[8], cp[8];
        const bool not_last = (st < T_STEPS - 1);
        if (is_mma) {
            #pragma unroll
            for (int j = 0; j < 4; j++) {
                float kk = keep[j];
                #pragma unroll
                for (int cc = 0; cc < 2; cc++) {
                    int e = (j & 1) * 2 + cc, mf = j >> 1, ix = j * 2 + cc;
                    float xg_i = cc ? xv[j][0].y : xv[j][0].x;
                    float xg_f = cc ? xv[j][1].y : xv[j][1].x;
                    float xg_g = cc ? xv[j][2].y : xv[j][2].x;
                    float xg_o = cc ? xv[j][3].y : xv[j][3].x;
                    float hpv = h_st[ix] * kk;
                    float cpv = c_st[ix] * kk;
                    float ii = sigm(acc[mf][0][e] + xg_i);
                    float ff = sigm(acc[mf][1][e] + xg_f);
                    float gg = tanhf(acc[mf][2][e] + xg_g);
                    float oo = sigm(acc[mf][3][e] + xg_o);
                    float cn = ff * cpv + ii * gg;
                    float hn = oo * tanhf(cn);
                    h_st[ix] = hn; c_st[ix] = cn; hp[ix] = hpv; cp[ix] = cpv;
                }
            }
            if (not_last) {
                // stage next-step h (pre-masked) as fp16 A-frags; slot == lane
                #pragma unroll
                for (int j = 0; j < 4; j++) {
                    float kn = 1.0f - (float)__ldg(&dones[(st + 1) * BATCH + rbase + 8 * j]);
                    __half2 hv = __floats2half2_rn(h_st[j * 2] * kn, h_st[j * 2 + 1] * kn);
                    int mt = j >> 1, rm = j & 1;
                    Stg[(((hg >> 1) * 2 + mt) * 128) + lane * 4 + ((hg & 1) << 1) + rm] =
                        *(unsigned*)&hv;
                    keep[j] = kn;
                }
            }
        }
        __syncthreads();                  // S1: Stg visible

        if (not_last && !is_mma) {
            // helpers: flush staged frags (2KB) to global double buffer
            unsigned* apd = g_APg + (((size_t)((st + 1) & 1) * 8 + bt) * 8192)
                          + (size_t)ht * 512;
            ((uint4*)apd)[htid] = ((const uint4*)Stg)[htid];
        }
        if (is_mma) {
            // outputs (overlap helper flush + barrier)
            const size_t hb = (size_t)st * 2 * BATCH * H_DIM;
            const size_t lb = (size_t)st * BATCH * H_DIM;
            #pragma unroll
            for (int j = 0; j < 4; j++) {
                const size_t ob = (size_t)(rbase + 8 * j) * H_DIM + c0;
                __stcs((float2*)&out_hidden[hb + ob],
                       make_float2(hp[j * 2], hp[j * 2 + 1]));
                __stcs((float2*)&out_hidden[hb + (size_t)BATCH * H_DIM + ob],
                       make_float2(cp[j * 2], cp[j * 2 + 1]));
                __stcs((float2*)&out_lstm[lb + ob],
                       make_float2(h_st[j * 2], h_st[j * 2 + 1]));
            }
        }

        if (not_last) {
            __syncthreads();              // S2: flush done
            if (tid == 128) {
                unsigned tgt = gbase + (unsigned)st + 1u;
                if (atom_add_acqrel(cnt, 1u) == 15u) {
                    *cnt = 0;
                    st_release(gen, tgt);
                }
                while (ld_acquire(gen) != tgt) { }
            }
            __syncthreads();              // S3: barrier passed
        }
    }
}

// ---------------- launch ----------------------------------------------------
extern "C" void kernel_launch(void* const* d_in, const int* in_sizes, int n_in,
                              void* d_out, int out_size) {
    const float* x     = (const float*)d_in[0];
    const int*   dones = (const int*)  d_in[1];
    const float* Wih   = (const float*)d_in[2];
    const float* Whh   = (const float*)d_in[3];
    const float* bih   = (const float*)d_in[4];
    const float* bhh   = (const float*)d_in[5];

    float* out_lstm   = (float*)d_out;
    float* out_hidden = out_lstm + (size_t)T_STEPS * BATCH * H_DIM;

    const int smem_xg   = XG_SMEM;                            // 204800 B
    const int smem_lstm = (32768 + 8192 + 512) * 4;           // 165888 B
    cudaFuncSetAttribute(xgemm_f16, cudaFuncAttributeMaxDynamicSharedMemorySize,
                         smem_xg);
    cudaFuncSetAttribute(lstm_tc, cudaFuncAttributeMaxDynamicSharedMemorySize,
                         smem_lstm);

    prep_x_frag<<<65536, 256>>>(x);
    prep_w_frag<<<2048, 256>>>(Wih);
    prep_hh<<<2048, 256>>>(Whh);

    xgemm_f16<<<512, 256, smem_xg>>>(bih, bhh);

    lstm_tc<<<128, 256, smem_lstm>>>(dones, out_lstm, out_hidden);
}

// round 15
// speedup vs baseline: 1.0610x; 1.0610x over previous
#include <cuda_runtime.h>
#include <cuda_fp16.h>
#include <math.h>
#include <stdint.h>

#define T_STEPS 256
#define BATCH   256
#define IN_DIM  512
#define H_DIM   512
#define GATES   2048

// ---------------- device scratch -------------------------------------------
__device__ float    g_Xg[(size_t)T_STEPS * BATCH * GATES];   // x@Wih^T + b (512MB)
__device__ unsigned g_xfr[(size_t)512 * 32 * 8 * 32 * 4];    // x fp16 A-frags (64MB)
__device__ unsigned g_wfr[64 * 4 * 32 * 32 * 2];             // Wih fp16 B-frags (2MB)
__device__ unsigned g_Wph[16 * 4 * 4 * 32 * 32 * 2];         // W_hh fp16 B-frags (2MB)
__device__ unsigned g_APg[2 * 8 * 32 * 2 * 32 * 4];          // fp16 h frags, dbl-buf
__device__ unsigned g_cnt[8 * 32];                           // per-group barrier
__device__ unsigned g_gen[8 * 32];

// ---------------- helpers --------------------------------------------------
__device__ __forceinline__ float sigm(float v) { return 1.0f / (1.0f + expf(-v)); }

__device__ __forceinline__ void mma_f16(float* c, uint4 A, uint2 B) {
    asm volatile(
        "mma.sync.aligned.m16n8k16.row.col.f32.f16.f16.f32 "
        "{%0,%1,%2,%3},{%4,%5,%6,%7},{%8,%9},{%0,%1,%2,%3};"
        : "+f"(c[0]), "+f"(c[1]), "+f"(c[2]), "+f"(c[3])
        : "r"(A.x), "r"(A.y), "r"(A.z), "r"(A.w), "r"(B.x), "r"(B.y));
}

__device__ __forceinline__ unsigned atom_add_acqrel(unsigned* p, unsigned v) {
    unsigned o;
    asm volatile("atom.acq_rel.gpu.global.add.u32 %0, [%1], %2;"
                 : "=r"(o) : "l"(p), "r"(v) : "memory");
    return o;
}
__device__ __forceinline__ void st_release(unsigned* p, unsigned v) {
    asm volatile("st.release.gpu.global.u32 [%0], %1;" :: "l"(p), "r"(v) : "memory");
}
__device__ __forceinline__ unsigned ld_acquire(const unsigned* p) {
    unsigned v;
    asm volatile("ld.acquire.gpu.global.u32 %0, [%1];" : "=r"(v) : "l"(p) : "memory");
    return v;
}

// ---------------- prep: x fp32 -> fp16 mma A-fragments ----------------------
// layout: [mtile 512][kb 32][mf 8][lane 32][reg 4] u32
__global__ void prep_x_frag(const float* __restrict__ x) {
    int id = blockIdx.x * blockDim.x + threadIdx.x;   // < 16777216
    int m = id >> 8, kp = id & 255;
    float2 v = ((const float2*)x)[(size_t)m * 256 + kp];
    __half2 h2 = __floats2half2_rn(v.x, v.y);
    int mtile = m >> 7, mf = (m >> 4) & 7, row = m & 15;
    int kb = kp >> 3;
    int lane = ((row & 7) << 2) | (kp & 3);
    int reg = ((row >> 3) & 1) | (((kp >> 2) & 1) << 1);
    g_xfr[((((size_t)mtile * 32 + kb) * 8 + mf) * 32 + lane) * 4 + reg] =
        *(unsigned*)&h2;
}

// ---------------- prep: Wih fp32 -> fp16 mma B-fragments --------------------
// layout: [ns 64][n8 4][kb 32][lane 32][reg 2] u32
__global__ void prep_w_frag(const float* __restrict__ Wih) {
    int id = blockIdx.x * blockDim.x + threadIdx.x;   // < 524288
    int n = id >> 8, kp = id & 255;
    float2 v = ((const float2*)Wih)[(size_t)n * 256 + kp];
    __half2 h2 = __floats2half2_rn(v.x, v.y);
    int ns = n >> 5, n8 = (n >> 3) & 3;
    int kb = kp >> 3;
    int lane = ((n & 7) << 2) | (kp & 3);
    int reg = (kp >> 2) & 1;
    g_wfr[((((size_t)ns * 4 + n8) * 32 + kb) * 32 + lane) * 2 + reg] =
        *(unsigned*)&h2;
}

// ---------------- prep: fp16 B-fragments for W_hh (lstm path) ---------------
__global__ void prep_hh(const float* __restrict__ Whh) {
    int t = blockIdx.x * blockDim.x + threadIdx.x;     // < 2^19
    int n = t >> 8, kp = t & 255, k = kp * 2;
    float2 wv = ((const float2*)Whh)[(size_t)n * 256 + kp];
    __half2 h2 = __floats2half2_rn(wv.x, wv.y);
    int g  = n >> 9, hh = n & 511;
    int ht = hh >> 5, hg = (hh >> 3) & 3;
    int kb16 = k >> 4;
    int lanei = ((n & 7) << 2) | ((k & 7) >> 1);
    int reg = (k >> 3) & 1;
    size_t bi = ((((size_t)(ht * 4 + g) * 4 + hg) * 32 + kb16) * 32 + lanei) * 2 + reg;
    g_Wph[bi] = *(unsigned*)&h2;
}

// ---------------- xgemm: fp16 mma.sync, m-stationary, 8 MMA + 4 copy warps --
// 512 blocks; block = 128 m-rows, A frags in smem (128KB).
// MMA warp = (mq = m32 strip, nh = n16 half of the 32-col slice): 2 warps per
// SMSP for latency hiding, 4 independent acc chains each. 4 copy warps stream
// W slices into a double buffer. 64 slices of 32 cols.
#define XG_SMEM ((32768 + 2 * 8192 + 2048) * 4)   // 200KB

__global__ __launch_bounds__(384, 1) void xgemm_f16(
    const float* __restrict__ bih, const float* __restrict__ bhh)
{
    extern __shared__ float sm_dyn[];
    unsigned* As = (unsigned*)sm_dyn;                // 32768 u32
    unsigned* Wb[2] = {As + 32768, As + 32768 + 8192};
    float* bias = (float*)(As + 32768 + 16384);      // 2048 f32

    const int tid = threadIdx.x, lane = tid & 31, w = tid >> 5;
    const int m0 = blockIdx.x * 128;
    const bool is_mma = (w < 8);
    const int mq = w >> 1, nh = w & 1;
    const int htid = tid - 256;                      // helper index 0..127

    // stage A fragments (verbatim copy), W slice 0, bias — all threads
    {
        const uint4* asrc = (const uint4*)g_xfr + (size_t)blockIdx.x * 8192;
        uint4* adst = (uint4*)As;
        #pragma unroll
        for (int i = 0; i < 22; i++) {
            int idx = tid + i * 384;
            if (idx < 8192) adst[idx] = __ldg(asrc + idx);
        }
        const uint4* wsrc = (const uint4*)g_wfr;
        uint4* wdst = (uint4*)Wb[0];
        #pragma unroll
        for (int i = 0; i < 6; i++) {
            int idx = tid + i * 384;
            if (idx < 2048) wdst[idx] = __ldg(wsrc + idx);
        }
        #pragma unroll
        for (int i = 0; i < 6; i++) {
            int n = tid + i * 384;
            if (n < 2048) bias[n] = __ldg(&bih[n]) + __ldg(&bhh[n]);
        }
    }
    __syncthreads();

    const int r = m0 + mq * 32 + (lane >> 2);
    const int cb = (lane & 3) * 2;

    for (int i = 0; i < 64; i++) {
        const int cur = i & 1;

        if (!is_mma) {
            // copy warps: prefetch next W slice into the other buffer
            if (i + 1 < 64) {
                const uint4* ws = (const uint4*)g_wfr + (size_t)(i + 1) * 2048;
                uint4* wd = (uint4*)Wb[cur ^ 1];
                #pragma unroll
                for (int j = 0; j < 16; j++)
                    wd[htid + j * 128] = __ldg(ws + htid + j * 128);
            }
        } else {
            float acc[2][2][4] = {};        // [mfrag][n8][creg]
            const unsigned* Wc = Wb[cur];
            #pragma unroll 8
            for (int kb = 0; kb < 32; kb++) {
                uint4 A0 = *(const uint4*)&As[((kb * 8 + mq * 2 + 0) * 32 + lane) * 4];
                uint4 A1 = *(const uint4*)&As[((kb * 8 + mq * 2 + 1) * 32 + lane) * 4];
                #pragma unroll
                for (int n8 = 0; n8 < 2; n8++) {
                    uint2 B = *(const uint2*)&Wc[(((nh * 2 + n8) * 32 + kb) * 32 + lane) * 2];
                    mma_f16(acc[0][n8], A0, B);
                    mma_f16(acc[1][n8], A1, B);
                }
            }
            // epilogue: +bias, streaming stores (g_Xg layout unchanged)
            const int c0 = i * 32 + nh * 16 + cb;
            #pragma unroll
            for (int n8 = 0; n8 < 2; n8++) {
                int c = c0 + n8 * 8;
                float b0 = bias[c], b1 = bias[c + 1];
                #pragma unroll
                for (int mf = 0; mf < 2; mf++) {
                    int row = r + mf * 16;
                    __stcs((float2*)&g_Xg[(size_t)row * GATES + c],
                           make_float2(acc[mf][n8][0] + b0, acc[mf][n8][1] + b1));
                    __stcs((float2*)&g_Xg[(size_t)(row + 8) * GATES + c],
                           make_float2(acc[mf][n8][2] + b0, acc[mf][n8][3] + b1));
                }
            }
        }
        __syncthreads();
    }
}

// ---------------- persistent LSTM recurrence (R13 structure, known-good) ----
// 128 blocks = 8 b-groups x 16 hh-tiles. Block tile: 32 b x 32 hh x 4 gates.
// warp w -> (m-half mh=w>>2, hh-octet hg=w&3), all 4 gates: MMA fragment
// ownership == epilogue ownership. W_hh slice resident in smem; h exchanged
// as pre-packed fp16 A-fragments via L2 with release/acquire group barrier.
__global__ __launch_bounds__(256, 1) void lstm_tc(
    const int*  __restrict__ dones,
    float* __restrict__ out_lstm,       // [T,B,H]
    float* __restrict__ out_hidden)     // [T,2,B,H]
{
    extern __shared__ float sm_dyn[];
    unsigned* Ws  = (unsigned*)sm_dyn;          // 32768 u32 (128KB)
    unsigned* APs = Ws + 32768;                 // 8192 u32  (32KB)
    unsigned* Stg = APs + 8192;                 // 512 u32   (2KB)

    const int tid = threadIdx.x, lane = tid & 31, w = tid >> 5;
    const int ht = blockIdx.x & 15, bt = blockIdx.x >> 4;
    const int hh0 = ht * 32, b0 = bt * 32;
    const int mh = w >> 2, hg = w & 3;

    const int r0 = b0 + mh * 16 + (lane >> 2);
    const int r1 = r0 + 8;
    const int c0 = hh0 + hg * 8 + (lane & 3) * 2;

    {
        const uint4* src = (const uint4*)(g_Wph + (size_t)ht * 32768);
        uint4* dst = (uint4*)Ws;
        #pragma unroll
        for (int i = 0; i < 32; i++) dst[tid + i * 256] = src[tid + i * 256];
    }
    __syncthreads();

    unsigned* cnt = &g_cnt[bt * 32];
    unsigned* gen = &g_gen[bt * 32];
    const unsigned gbase = ld_acquire(gen);

    const int slot = (((hg >> 1) * 2 + mh) * 128) + lane * 4 + ((hg & 1) << 1);

    float h_st[4] = {0.f,0.f,0.f,0.f};
    float c_st[4] = {0.f,0.f,0.f,0.f};
    float keep0 = 1.0f - (float)__ldg(&dones[r0]);
    float keep1 = 1.0f - (float)__ldg(&dones[r1]);

    for (int st = 0; st < T_STEPS; st++) {
        const float* xgr0 = g_Xg + ((size_t)st * BATCH + r0) * GATES + c0;
        const float* xgr1 = g_Xg + ((size_t)st * BATCH + r1) * GATES + c0;
        float2 xv0[4], xv1[4];
        #pragma unroll
        for (int g = 0; g < 4; g++) {
            xv0[g] = __ldcs((const float2*)(xgr0 + g * H_DIM));
            xv1[g] = __ldcs((const float2*)(xgr1 + g * H_DIM));
        }

        float acc[4][4] = {};
        if (st > 0) {
            const uint4* asrc = (const uint4*)(g_APg + ((size_t)(st & 1) * 8 + bt) * 8192);
            uint4* adst = (uint4*)APs;
            #pragma unroll
            for (int i = 0; i < 8; i++)
                adst[tid + i * 256] = __ldcg(asrc + tid + i * 256);
            __syncthreads();

            #pragma unroll 4
            for (int kb = 0; kb < 32; kb++) {
                uint4 A = *(const uint4*)&APs[((kb * 2 + mh) * 32 + lane) * 4];
                #pragma unroll
                for (int g = 0; g < 4; g++) {
                    uint2 B = *(const uint2*)&Ws[(((g * 4 + hg) * 32 + kb) * 32 + lane) * 2];
                    mma_f16(acc[g], A, B);
                }
            }
        }

        float xa[4][4];
        #pragma unroll
        for (int g = 0; g < 4; g++) {
            xa[g][0] = xv0[g].x; xa[g][1] = xv0[g].y;
            xa[g][2] = xv1[g].x; xa[g][3] = xv1[g].y;
        }
        float hp[4], cp[4];
        #pragma unroll
        for (int i = 0; i < 4; i++) {
            float k_ = (i < 2) ? keep0 : keep1;
            float hpv = h_st[i] * k_;
            float cpv = c_st[i] * k_;
            float ii = sigm(acc[0][i] + xa[0][i]);
            float ff = sigm(acc[1][i] + xa[1][i]);
            float gg = tanhf(acc[2][i] + xa[2][i]);
            float oo = sigm(acc[3][i] + xa[3][i]);
            float cn = ff * cpv + ii * gg;
            float hn = oo * tanhf(cn);
            h_st[i] = hn; c_st[i] = cn; hp[i] = hpv; cp[i] = cpv;
        }

        bool not_last = (st < T_STEPS - 1);
        unsigned tgt = gbase + (unsigned)st + 1u;
        if (not_last) {
            float kn0 = 1.0f - (float)__ldg(&dones[(st + 1) * BATCH + r0]);
            float kn1 = 1.0f - (float)__ldg(&dones[(st + 1) * BATCH + r1]);
            __half2 w0 = __floats2half2_rn(h_st[0] * kn0, h_st[1] * kn0);
            __half2 w1 = __floats2half2_rn(h_st[2] * kn1, h_st[3] * kn1);
            Stg[slot]     = *(unsigned*)&w0;
            Stg[slot + 1] = *(unsigned*)&w1;
            keep0 = kn0; keep1 = kn1;
            __syncthreads();
            unsigned* apd = g_APg + (((size_t)((st + 1) & 1) * 8 + bt) * 8192)
                          + (size_t)ht * 512;
            if (tid < 128)
                ((uint4*)apd)[tid] = ((const uint4*)Stg)[tid];
            __syncthreads();
            if (tid == 0) {
                if (atom_add_acqrel(cnt, 1u) == 15u) {
                    *cnt = 0;
                    st_release(gen, tgt);
                }
            }
        }

        const size_t ob0 = (size_t)r0 * H_DIM + c0;
        const size_t ob1 = (size_t)r1 * H_DIM + c0;
        const size_t hb  = (size_t)st * 2 * BATCH * H_DIM;
        const size_t lb  = (size_t)st * BATCH * H_DIM;
        __stcs((float2*)&out_hidden[hb + ob0],                       make_float2(hp[0], hp[1]));
        __stcs((float2*)&out_hidden[hb + ob1],                       make_float2(hp[2], hp[3]));
        __stcs((float2*)&out_hidden[hb + (size_t)BATCH*H_DIM + ob0], make_float2(cp[0], cp[1]));
        __stcs((float2*)&out_hidden[hb + (size_t)BATCH*H_DIM + ob1], make_float2(cp[2], cp[3]));
        __stcs((float2*)&out_lstm[lb + ob0],                         make_float2(h_st[0], h_st[1]));
        __stcs((float2*)&out_lstm[lb + ob1],                         make_float2(h_st[2], h_st[3]));

        if (not_last) {
            if (tid == 0) {
                while (ld_acquire(gen) != tgt) { }
            }
            __syncthreads();
        }
    }
}

// ---------------- launch ----------------------------------------------------
extern "C" void kernel_launch(void* const* d_in, const int* in_sizes, int n_in,
                              void* d_out, int out_size) {
    const float* x     = (const float*)d_in[0];
    const int*   dones = (const int*)  d_in[1];
    const float* Wih   = (const float*)d_in[2];
    const float* Whh   = (const float*)d_in[3];
    const float* bih   = (const float*)d_in[4];
    const float* bhh   = (const float*)d_in[5];

    float* out_lstm   = (float*)d_out;
    float* out_hidden = out_lstm + (size_t)T_STEPS * BATCH * H_DIM;

    const int smem_xg   = XG_SMEM;                            // 204800 B
    const int smem_lstm = (32768 + 8192 + 512) * 4;           // 165888 B
    cudaFuncSetAttribute(xgemm_f16, cudaFuncAttributeMaxDynamicSharedMemorySize,
                         smem_xg);
    cudaFuncSetAttribute(lstm_tc, cudaFuncAttributeMaxDynamicSharedMemorySize,
                         smem_lstm);

    prep_x_frag<<<65536, 256>>>(x);
    prep_w_frag<<<2048, 256>>>(Wih);
    prep_hh<<<2048, 256>>>(Whh);

    xgemm_f16<<<512, 384, smem_xg>>>(bih, bhh);

    lstm_tc<<<128, 256, smem_lstm>>>(dones, out_lstm, out_hidden);
}